// round 1
// baseline (speedup 1.0000x reference)
#include <cuda_runtime.h>
#include <cstdint>

// Problem sizes (fixed by the reference)
#define M_ROWS 8192
#define IN_F   512
#define OUT_F  512
#define KDIM   (IN_F * 8)   // 4096 (8 bases per input feature)

// ---------------------------------------------------------------------------
// Device scratch (allocation-free rule: __device__ globals)
// ---------------------------------------------------------------------------
__device__ __align__(16) float g_A[(size_t)M_ROWS * KDIM]; // 128 MB bases (tf32-rounded)
__device__ __align__(16) float g_W[(size_t)OUT_F * KDIM];  //   8 MB packed coeffs W[o][k]

__device__ __forceinline__ float to_tf32(float x) {
    uint32_t u;
    asm("cvt.rna.tf32.f32 %0, %1;" : "=r"(u) : "f"(x));
    return __uint_as_float(u);
}

// ---------------------------------------------------------------------------
// Kernel 1: bases.  Uniform cubic B-spline closed form.
// A[b, i*8 + j] for j in [0,7], only 4 nonzero at j0..j0+3, j0 = m-3.
// ---------------------------------------------------------------------------
__global__ void basis_kernel(const float* __restrict__ x,
                             const float* __restrict__ grid) {
    int idx = blockIdx.x * blockDim.x + threadIdx.x;
    if (idx >= M_ROWS * IN_F) return;

    float g0   = __ldg(grid);
    float invh = 1.0f / (__ldg(grid + 1) - g0);

    float xn = tanhf(x[idx]);
    float t  = (xn - g0) * invh;
    int   m  = (int)floorf(t);
    m = min(max(m, 3), 7);          // xn in (-1,1) -> m in [3,7]; clamp for safety
    float u  = t - (float)m;

    float um = 1.0f - u;
    float u2 = u * u, u3 = u2 * u;
    const float s = 1.0f / 6.0f;
    float w0 = um * um * um * s;
    float w1 = (3.0f * u3 - 6.0f * u2 + 4.0f) * s;
    float w2 = (-3.0f * u3 + 3.0f * u2 + 3.0f * u + 1.0f) * s;
    float w3 = u3 * s;
    int j0 = m - 3;                 // in [0,4]

    float v[8];
#pragma unroll
    for (int k = 0; k < 8; ++k) {
        int r = k - j0;
        float val = (r == 0) ? w0 : (r == 1) ? w1 : (r == 2) ? w2 : (r == 3) ? w3 : 0.0f;
        v[k] = to_tf32(val);
    }
    float4* dst = reinterpret_cast<float4*>(g_A + (size_t)idx * 8);
    dst[0] = make_float4(v[0], v[1], v[2], v[3]);
    dst[1] = make_float4(v[4], v[5], v[6], v[7]);
}

// ---------------------------------------------------------------------------
// Kernel 2: pack W[o][i*8+k] = C[i][o][k], tf32-rounded.
// ---------------------------------------------------------------------------
__global__ void wpack_kernel(const float* __restrict__ coef) {
    int t = blockIdx.x * blockDim.x + threadIdx.x;
    if (t >= IN_F * OUT_F) return;
    int i = t & (IN_F - 1);
    int o = t >> 9;

    const float4* src = reinterpret_cast<const float4*>(coef + ((size_t)i * OUT_F + o) * 8);
    float4 c0 = __ldg(src);
    float4 c1 = __ldg(src + 1);

    float4 d0 = make_float4(to_tf32(c0.x), to_tf32(c0.y), to_tf32(c0.z), to_tf32(c0.w));
    float4 d1 = make_float4(to_tf32(c1.x), to_tf32(c1.y), to_tf32(c1.z), to_tf32(c1.w));

    float4* dst = reinterpret_cast<float4*>(g_W + (size_t)o * KDIM + i * 8);
    dst[0] = d0;
    dst[1] = d1;
}

// ---------------------------------------------------------------------------
// Kernel 3: GEMM  out[M,N] = A[M,K] @ W^T   (W stored [N][K] -> B col-major)
// mma.sync.m16n8k8 tf32, fp32 accumulate. BM=128 BN=128 BK=16, 256 threads,
// 8 warps in 2x4, warp tile 64x32 (4 m-tiles x 4 n-tiles).
// ---------------------------------------------------------------------------
#define BM 128
#define BN 128
#define BK 16
#define PAD 4
#define KT (KDIM / BK)   // 256

__device__ __forceinline__ void cp16(void* smem, const void* gmem) {
    uint32_t sa = (uint32_t)__cvta_generic_to_shared(smem);
    asm volatile("cp.async.ca.shared.global [%0], [%1], 16;\n" :: "r"(sa), "l"(gmem));
}

__device__ __forceinline__ void mma_tf32(float (&d)[4], const uint32_t (&a)[4],
                                         const uint32_t (&b)[2]) {
    asm volatile(
        "mma.sync.aligned.m16n8k8.row.col.f32.tf32.tf32.f32 "
        "{%0,%1,%2,%3}, {%4,%5,%6,%7}, {%8,%9}, {%0,%1,%2,%3};"
        : "+f"(d[0]), "+f"(d[1]), "+f"(d[2]), "+f"(d[3])
        : "r"(a[0]), "r"(a[1]), "r"(a[2]), "r"(a[3]), "r"(b[0]), "r"(b[1]));
}

__global__ void __launch_bounds__(256) gemm_kernel(float* __restrict__ C) {
    __shared__ float As[2][BM][BK + PAD];
    __shared__ float Bs[2][BN][BK + PAD];

    const int tid  = threadIdx.x;
    const int bm   = blockIdx.y * BM;
    const int bn   = blockIdx.x * BN;
    const int wid  = tid >> 5;
    const int lane = tid & 31;
    const int wm   = (wid >> 2) * 64;   // warp row offset: 0 / 64
    const int wn   = (wid & 3) * 32;    // warp col offset: 0..96
    const int gID  = lane >> 2;         // 0..7
    const int tg   = lane & 3;          // 0..3

    const int lr = tid >> 2;            // load row 0..63
    const int lc = (tid & 3) * 4;       // load col 0,4,8,12

    float acc[4][4][4];
#pragma unroll
    for (int a = 0; a < 4; ++a)
#pragma unroll
        for (int b = 0; b < 4; ++b)
#pragma unroll
            for (int c = 0; c < 4; ++c) acc[a][b][c] = 0.0f;

    auto issue = [&](int buf, int kt) {
        int k0 = kt * BK;
        const float* aptr = g_A + (size_t)(bm + lr) * KDIM + k0 + lc;
        cp16(&As[buf][lr][lc],      aptr);
        cp16(&As[buf][lr + 64][lc], aptr + (size_t)64 * KDIM);
        const float* bptr = g_W + (size_t)(bn + lr) * KDIM + k0 + lc;
        cp16(&Bs[buf][lr][lc],      bptr);
        cp16(&Bs[buf][lr + 64][lc], bptr + (size_t)64 * KDIM);
        asm volatile("cp.async.commit_group;\n");
    };

    issue(0, 0);

    for (int kt = 0; kt < KT; ++kt) {
        int buf = kt & 1;
        if (kt + 1 < KT) {
            issue(buf ^ 1, kt + 1);
            asm volatile("cp.async.wait_group 1;\n");
        } else {
            asm volatile("cp.async.wait_group 0;\n");
        }
        __syncthreads();

#pragma unroll
        for (int ks = 0; ks < BK; ks += 8) {
            uint32_t af[4][4];
#pragma unroll
            for (int mt = 0; mt < 4; ++mt) {
                int r = wm + mt * 16 + gID;
                af[mt][0] = __float_as_uint(As[buf][r][ks + tg]);
                af[mt][1] = __float_as_uint(As[buf][r + 8][ks + tg]);
                af[mt][2] = __float_as_uint(As[buf][r][ks + tg + 4]);
                af[mt][3] = __float_as_uint(As[buf][r + 8][ks + tg + 4]);
            }
            uint32_t bf[4][2];
#pragma unroll
            for (int nt = 0; nt < 4; ++nt) {
                int c = wn + nt * 8 + gID;
                bf[nt][0] = __float_as_uint(Bs[buf][c][ks + tg]);
                bf[nt][1] = __float_as_uint(Bs[buf][c][ks + tg + 4]);
            }
#pragma unroll
            for (int mt = 0; mt < 4; ++mt)
#pragma unroll
                for (int nt = 0; nt < 4; ++nt)
                    mma_tf32(acc[mt][nt], af[mt], bf[nt]);
        }
        __syncthreads();
    }

    // Epilogue: direct fp32 stores (single K-pass, no partials).
#pragma unroll
    for (int mt = 0; mt < 4; ++mt) {
        int r0 = bm + wm + mt * 16 + gID;
#pragma unroll
        for (int nt = 0; nt < 4; ++nt) {
            int c = bn + wn + nt * 8 + tg * 2;
            *reinterpret_cast<float2*>(C + (size_t)r0 * OUT_F + c) =
                make_float2(acc[mt][nt][0], acc[mt][nt][1]);
            *reinterpret_cast<float2*>(C + (size_t)(r0 + 8) * OUT_F + c) =
                make_float2(acc[mt][nt][2], acc[mt][nt][3]);
        }
    }
}

// ---------------------------------------------------------------------------
extern "C" void kernel_launch(void* const* d_in, const int* in_sizes, int n_in,
                              void* d_out, int out_size) {
    const float* x    = (const float*)d_in[0];
    const float* coef = (const float*)d_in[1];
    const float* grid = (const float*)d_in[2];
    float* out = (float*)d_out;

    basis_kernel<<<(M_ROWS * IN_F + 255) / 256, 256>>>(x, grid);
    wpack_kernel<<<(IN_F * OUT_F + 255) / 256, 256>>>(coef);

    dim3 g(OUT_F / BN, M_ROWS / BM);  // (4, 64)
    gemm_kernel<<<g, 256>>>(out);
}

// round 3
// speedup vs baseline: 1.0634x; 1.0634x over previous
#include <cuda_runtime.h>
#include <cstdint>

// Problem sizes (fixed by the reference)
#define M_ROWS 8192
#define IN_F   512
#define OUT_F  512
#define KDIM   (IN_F * 8)   // 4096

// ---------------------------------------------------------------------------
// Device scratch (allocation-free rule: __device__ globals)
// ---------------------------------------------------------------------------
__device__ __align__(16) float g_A[(size_t)M_ROWS * KDIM]; // 128 MB bases (tf32-rounded)
__device__ __align__(16) float g_W[(size_t)OUT_F * KDIM];  //   8 MB packed coeffs

__device__ __forceinline__ float to_tf32(float x) {
    uint32_t u;
    asm("cvt.rna.tf32.f32 %0, %1;" : "=r"(u) : "f"(x));
    return __uint_as_float(u);
}

// ---------------------------------------------------------------------------
// Kernel 1: bases (uniform cubic B-spline closed form).
// ---------------------------------------------------------------------------
__global__ void basis_kernel(const float* __restrict__ x,
                             const float* __restrict__ grid) {
    int idx = blockIdx.x * blockDim.x + threadIdx.x;
    if (idx >= M_ROWS * IN_F) return;

    float g0   = __ldg(grid);
    float invh = 1.0f / (__ldg(grid + 1) - g0);

    float xn = tanhf(x[idx]);
    float t  = (xn - g0) * invh;
    int   m  = (int)floorf(t);
    m = min(max(m, 3), 7);
    float u  = t - (float)m;

    float um = 1.0f - u;
    float u2 = u * u, u3 = u2 * u;
    const float s = 1.0f / 6.0f;
    float w0 = um * um * um * s;
    float w1 = (3.0f * u3 - 6.0f * u2 + 4.0f) * s;
    float w2 = (-3.0f * u3 + 3.0f * u2 + 3.0f * u + 1.0f) * s;
    float w3 = u3 * s;
    int j0 = m - 3;

    float v[8];
#pragma unroll
    for (int k = 0; k < 8; ++k) {
        int r = k - j0;
        float val = (r == 0) ? w0 : (r == 1) ? w1 : (r == 2) ? w2 : (r == 3) ? w3 : 0.0f;
        v[k] = to_tf32(val);
    }
    float4* dst = reinterpret_cast<float4*>(g_A + (size_t)idx * 8);
    dst[0] = make_float4(v[0], v[1], v[2], v[3]);
    dst[1] = make_float4(v[4], v[5], v[6], v[7]);
}

// ---------------------------------------------------------------------------
// Kernel 2: pack W[o][i*8+k] = C[i][o][k], tf32-rounded.
// ---------------------------------------------------------------------------
__global__ void wpack_kernel(const float* __restrict__ coef) {
    int t = blockIdx.x * blockDim.x + threadIdx.x;
    if (t >= IN_F * OUT_F) return;
    int i = t & (IN_F - 1);
    int o = t >> 9;

    const float4* src = reinterpret_cast<const float4*>(coef + ((size_t)i * OUT_F + o) * 8);
    float4 c0 = __ldg(src);
    float4 c1 = __ldg(src + 1);

    float4 d0 = make_float4(to_tf32(c0.x), to_tf32(c0.y), to_tf32(c0.z), to_tf32(c0.w));
    float4 d1 = make_float4(to_tf32(c1.x), to_tf32(c1.y), to_tf32(c1.z), to_tf32(c1.w));

    float4* dst = reinterpret_cast<float4*>(g_W + (size_t)o * KDIM + i * 8);
    dst[0] = d0;
    dst[1] = d1;
}

// ---------------------------------------------------------------------------
// Kernel 3: GEMM  out[M,N] = A[M,K] @ W^T  via mma.sync m16n8k8 tf32.
// CTA tile 128x256, BK=16, 3-stage cp.async pipeline, 8 warps (2x4) with
// 64x64 warp tiles (4 m-tiles x 8 n-tiles). 128 CTAs = one wave.
// ---------------------------------------------------------------------------
#define BM 128
#define BN 256
#define BK 16
#define ROWW (BK + 4)                 // padded row: 20 floats, conflict-free
#define STAGES 3
#define KT (KDIM / BK)                // 256
#define A_STAGE (BM * ROWW)           // floats per A stage
#define B_STAGE (BN * ROWW)
#define SMEM_FLOATS (STAGES * (A_STAGE + B_STAGE))

__device__ __forceinline__ void cp16(void* smem, const void* gmem) {
    uint32_t sa = (uint32_t)__cvta_generic_to_shared(smem);
    asm volatile("cp.async.cg.shared.global [%0], [%1], 16;\n" :: "r"(sa), "l"(gmem));
}

__device__ __forceinline__ void mma_tf32(float (&d)[4], const uint32_t (&a)[4],
                                         const uint32_t (&b)[2]) {
    asm volatile(
        "mma.sync.aligned.m16n8k8.row.col.f32.tf32.tf32.f32 "
        "{%0,%1,%2,%3}, {%4,%5,%6,%7}, {%8,%9}, {%0,%1,%2,%3};"
        : "+f"(d[0]), "+f"(d[1]), "+f"(d[2]), "+f"(d[3])
        : "r"(a[0]), "r"(a[1]), "r"(a[2]), "r"(a[3]), "r"(b[0]), "r"(b[1]));
}

__global__ void __launch_bounds__(256, 1) gemm_kernel(float* __restrict__ C) {
    extern __shared__ float sm[];
    float* AsBase = sm;                       // [STAGES][BM][ROWW]
    float* BsBase = sm + STAGES * A_STAGE;    // [STAGES][BN][ROWW]

    const int tid  = threadIdx.x;
    const int bm   = blockIdx.y * BM;
    const int bn   = blockIdx.x * BN;
    const int wid  = tid >> 5;
    const int lane = tid & 31;
    const int wm   = (wid >> 2) * 64;   // 0 / 64
    const int wn   = (wid & 3) * 64;    // 0..192
    const int gID  = lane >> 2;         // 0..7
    const int tg   = lane & 3;          // 0..3

    const int lr = tid >> 2;            // load row 0..63
    const int lc = (tid & 3) * 4;       // load col 0,4,8,12

    float acc[4][8][4];
#pragma unroll
    for (int a = 0; a < 4; ++a)
#pragma unroll
        for (int b = 0; b < 8; ++b)
#pragma unroll
            for (int c = 0; c < 4; ++c) acc[a][b][c] = 0.0f;

    auto issue = [&](int s, int kt) {
        int k0 = kt * BK;
        float* As = AsBase + s * A_STAGE;
        float* Bs = BsBase + s * B_STAGE;
        const float* aptr = g_A + (size_t)(bm + lr) * KDIM + k0 + lc;
        cp16(As + lr * ROWW + lc,        aptr);
        cp16(As + (lr + 64) * ROWW + lc, aptr + (size_t)64 * KDIM);
        const float* bptr = g_W + (size_t)(bn + lr) * KDIM + k0 + lc;
        cp16(Bs + lr * ROWW + lc,         bptr);
        cp16(Bs + (lr + 64) * ROWW + lc,  bptr + (size_t)64 * KDIM);
        cp16(Bs + (lr + 128) * ROWW + lc, bptr + (size_t)128 * KDIM);
        cp16(Bs + (lr + 192) * ROWW + lc, bptr + (size_t)192 * KDIM);
        asm volatile("cp.async.commit_group;\n");
    };

    issue(0, 0);
    issue(1, 1);

    for (int kt = 0; kt < KT; ++kt) {
        if (kt < KT - 1) {
            asm volatile("cp.async.wait_group 1;\n");
        } else {
            asm volatile("cp.async.wait_group 0;\n");
        }
        __syncthreads();

        if (kt + 2 < KT) issue((kt + 2) % STAGES, kt + 2);

        const float* As = AsBase + (kt % STAGES) * A_STAGE;
        const float* Bs = BsBase + (kt % STAGES) * B_STAGE;

#pragma unroll
        for (int ks = 0; ks < BK; ks += 8) {
            uint32_t af[4][4];
#pragma unroll
            for (int mt = 0; mt < 4; ++mt) {
                const float* ap = As + (wm + mt * 16 + gID) * ROWW + ks + tg;
                af[mt][0] = __float_as_uint(ap[0]);
                af[mt][1] = __float_as_uint(ap[8 * ROWW]);
                af[mt][2] = __float_as_uint(ap[4]);
                af[mt][3] = __float_as_uint(ap[8 * ROWW + 4]);
            }
            uint32_t bf[8][2];
#pragma unroll
            for (int nt = 0; nt < 8; ++nt) {
                const float* bp = Bs + (wn + nt * 8 + gID) * ROWW + ks + tg;
                bf[nt][0] = __float_as_uint(bp[0]);
                bf[nt][1] = __float_as_uint(bp[4]);
            }
#pragma unroll
            for (int mt = 0; mt < 4; ++mt)
#pragma unroll
                for (int nt = 0; nt < 8; ++nt)
                    mma_tf32(acc[mt][nt], af[mt], bf[nt]);
        }
        __syncthreads();
    }

    // Epilogue: direct fp32 stores.
#pragma unroll
    for (int mt = 0; mt < 4; ++mt) {
        int r0 = bm + wm + mt * 16 + gID;
#pragma unroll
        for (int nt = 0; nt < 8; ++nt) {
            int c = bn + wn + nt * 8 + tg * 2;
            *reinterpret_cast<float2*>(C + (size_t)r0 * OUT_F + c) =
                make_float2(acc[mt][nt][0], acc[mt][nt][1]);
            *reinterpret_cast<float2*>(C + (size_t)(r0 + 8) * OUT_F + c) =
                make_float2(acc[mt][nt][2], acc[mt][nt][3]);
        }
    }
}

// ---------------------------------------------------------------------------
extern "C" void kernel_launch(void* const* d_in, const int* in_sizes, int n_in,
                              void* d_out, int out_size) {
    const float* x    = (const float*)d_in[0];
    const float* coef = (const float*)d_in[1];
    const float* grid = (const float*)d_in[2];
    float* out = (float*)d_out;

    basis_kernel<<<(M_ROWS * IN_F + 255) / 256, 256>>>(x, grid);
    wpack_kernel<<<(IN_F * OUT_F + 255) / 256, 256>>>(coef);

    static int smem_set = 0;
    if (!smem_set) {
        cudaFuncSetAttribute(gemm_kernel, cudaFuncAttributeMaxDynamicSharedMemorySize,
                             SMEM_FLOATS * sizeof(float));
        smem_set = 1;
    }
    dim3 g(OUT_F / BN, M_ROWS / BM);   // (2, 64) = 128 CTAs, one wave
    gemm_kernel<<<g, 256, SMEM_FLOATS * sizeof(float)>>>(out);
}

// round 4
// speedup vs baseline: 1.9359x; 1.8206x over previous
#include <cuda_runtime.h>
#include <cuda_fp16.h>
#include <cstdint>

// Problem sizes (fixed by the reference)
#define M_ROWS 8192
#define IN_F   512
#define OUT_F  512
#define KDIM   (IN_F * 8)   // 4096

// ---------------------------------------------------------------------------
// Device scratch (allocation-free rule: __device__ globals)
// ---------------------------------------------------------------------------
__device__ __align__(16) __half g_Ah[(size_t)M_ROWS * KDIM]; // 64 MB bases (fp16)
__device__ __align__(16) __half g_Wh[(size_t)OUT_F * KDIM];  //  4 MB packed coeffs

// ---------------------------------------------------------------------------
// Kernel 1: bases (uniform cubic B-spline closed form), fp16 output.
// tanh via exp2-path MUFU: tanh(x) = 1 - 2/(exp(2x)+1)  (~1e-6 abs err).
// ---------------------------------------------------------------------------
__global__ void basis_kernel(const float* __restrict__ x,
                             const float* __restrict__ grid) {
    int idx = blockIdx.x * blockDim.x + threadIdx.x;
    if (idx >= M_ROWS * IN_F) return;

    float g0   = __ldg(grid);
    float invh = 1.0f / (__ldg(grid + 1) - g0);

    float xv = x[idx];
    float e  = __expf(2.0f * xv);
    float xn = 1.0f - 2.0f / (e + 1.0f);   // == tanh(xv); saturates correctly at +/-inf

    float t  = (xn - g0) * invh;
    int   m  = (int)floorf(t);
    m = min(max(m, 3), 7);
    float u  = t - (float)m;

    float um = 1.0f - u;
    float u2 = u * u, u3 = u2 * u;
    const float s = 1.0f / 6.0f;
    float w0 = um * um * um * s;
    float w1 = (3.0f * u3 - 6.0f * u2 + 4.0f) * s;
    float w2 = (-3.0f * u3 + 3.0f * u2 + 3.0f * u + 1.0f) * s;
    float w3 = u3 * s;
    int j0 = m - 3;

    float v[8];
#pragma unroll
    for (int k = 0; k < 8; ++k) {
        int r = k - j0;
        v[k] = (r == 0) ? w0 : (r == 1) ? w1 : (r == 2) ? w2 : (r == 3) ? w3 : 0.0f;
    }
    __half2 h0 = __floats2half2_rn(v[0], v[1]);
    __half2 h1 = __floats2half2_rn(v[2], v[3]);
    __half2 h2 = __floats2half2_rn(v[4], v[5]);
    __half2 h3 = __floats2half2_rn(v[6], v[7]);
    uint4 pack = make_uint4(*(uint32_t*)&h0, *(uint32_t*)&h1,
                            *(uint32_t*)&h2, *(uint32_t*)&h3);
    *reinterpret_cast<uint4*>(g_Ah + (size_t)idx * 8) = pack;
}

// ---------------------------------------------------------------------------
// Kernel 2: pack W[o][i*8+k] = C[i][o][k], fp16.
// ---------------------------------------------------------------------------
__global__ void wpack_kernel(const float* __restrict__ coef) {
    int t = blockIdx.x * blockDim.x + threadIdx.x;
    if (t >= IN_F * OUT_F) return;
    int i = t & (IN_F - 1);
    int o = t >> 9;

    const float4* src = reinterpret_cast<const float4*>(coef + ((size_t)i * OUT_F + o) * 8);
    float4 c0 = __ldg(src);
    float4 c1 = __ldg(src + 1);

    __half2 h0 = __floats2half2_rn(c0.x, c0.y);
    __half2 h1 = __floats2half2_rn(c0.z, c0.w);
    __half2 h2 = __floats2half2_rn(c1.x, c1.y);
    __half2 h3 = __floats2half2_rn(c1.z, c1.w);
    uint4 pack = make_uint4(*(uint32_t*)&h0, *(uint32_t*)&h1,
                            *(uint32_t*)&h2, *(uint32_t*)&h3);
    *reinterpret_cast<uint4*>(g_Wh + (size_t)o * KDIM + i * 8) = pack;
}

// ---------------------------------------------------------------------------
// Kernel 3: GEMM  out[M,N] = A[M,K] @ W^T  via mma.sync m16n8k16 fp16->fp32.
// CTA tile 128x256, BK=32 halves, 3-stage cp.async pipeline, 8 warps (2x4)
// with 64x64 warp tiles. 128 CTAs = one wave.
// ---------------------------------------------------------------------------
#define BM 128
#define BN 256
#define BK 32                         // halves per K chunk
#define ROWH 40                       // padded row in halves (80B) - conflict-free
#define STAGES 3
#define KT (KDIM / BK)                // 128
#define A_ST (BM * ROWH)              // halves per A stage
#define B_ST (BN * ROWH)
#define SMEM_BYTES (STAGES * (A_ST + B_ST) * 2)

__device__ __forceinline__ void cp16(void* smem, const void* gmem) {
    uint32_t sa = (uint32_t)__cvta_generic_to_shared(smem);
    asm volatile("cp.async.cg.shared.global [%0], [%1], 16;\n" :: "r"(sa), "l"(gmem));
}

__device__ __forceinline__ void mma_f16(float (&d)[4], const uint32_t (&a)[4],
                                        const uint32_t (&b)[2]) {
    asm volatile(
        "mma.sync.aligned.m16n8k16.row.col.f32.f16.f16.f32 "
        "{%0,%1,%2,%3}, {%4,%5,%6,%7}, {%8,%9}, {%0,%1,%2,%3};"
        : "+f"(d[0]), "+f"(d[1]), "+f"(d[2]), "+f"(d[3])
        : "r"(a[0]), "r"(a[1]), "r"(a[2]), "r"(a[3]), "r"(b[0]), "r"(b[1]));
}

__global__ void __launch_bounds__(256, 1) gemm_kernel(float* __restrict__ C) {
    extern __shared__ __half sm[];
    __half* AsBase = sm;                      // [STAGES][BM][ROWH]
    __half* BsBase = sm + STAGES * A_ST;      // [STAGES][BN][ROWH]

    const int tid  = threadIdx.x;
    const int bm   = blockIdx.y * BM;
    const int bn   = blockIdx.x * BN;
    const int wid  = tid >> 5;
    const int lane = tid & 31;
    const int wm   = (wid >> 2) * 64;   // 0 / 64
    const int wn   = (wid & 3) * 64;    // 0..192
    const int gID  = lane >> 2;         // 0..7
    const int tg   = lane & 3;          // 0..3

    float acc[4][8][4];
#pragma unroll
    for (int a = 0; a < 4; ++a)
#pragma unroll
        for (int b = 0; b < 8; ++b)
#pragma unroll
            for (int c = 0; c < 4; ++c) acc[a][b][c] = 0.0f;

    auto issue = [&](int s, int kt) {
        int k0 = kt * BK;
        __half* As = AsBase + s * A_ST;
        __half* Bs = BsBase + s * B_ST;
#pragma unroll
        for (int i = 0; i < 2; ++i) {            // A: 512 16B-chunks
            int id = tid + 256 * i;
            int r = id >> 2, c = id & 3;
            cp16(As + r * ROWH + c * 8, g_Ah + (size_t)(bm + r) * KDIM + k0 + c * 8);
        }
#pragma unroll
        for (int i = 0; i < 4; ++i) {            // B: 1024 16B-chunks
            int id = tid + 256 * i;
            int r = id >> 2, c = id & 3;
            cp16(Bs + r * ROWH + c * 8, g_Wh + (size_t)(bn + r) * KDIM + k0 + c * 8);
        }
        asm volatile("cp.async.commit_group;\n");
    };

    issue(0, 0);
    issue(1, 1);

    for (int kt = 0; kt < KT; ++kt) {
        if (kt < KT - 1) {
            asm volatile("cp.async.wait_group 1;\n");
        } else {
            asm volatile("cp.async.wait_group 0;\n");
        }
        __syncthreads();

        if (kt + 2 < KT) issue((kt + 2) % STAGES, kt + 2);

        const __half* As = AsBase + (kt % STAGES) * A_ST;
        const __half* Bs = BsBase + (kt % STAGES) * B_ST;

#pragma unroll
        for (int ks = 0; ks < BK; ks += 16) {
            uint32_t af[4][4];
#pragma unroll
            for (int mt = 0; mt < 4; ++mt) {
                const __half* ap = As + (wm + mt * 16 + gID) * ROWH + ks + 2 * tg;
                af[mt][0] = *reinterpret_cast<const uint32_t*>(ap);
                af[mt][1] = *reinterpret_cast<const uint32_t*>(ap + 8 * ROWH);
                af[mt][2] = *reinterpret_cast<const uint32_t*>(ap + 8);
                af[mt][3] = *reinterpret_cast<const uint32_t*>(ap + 8 * ROWH + 8);
            }
            uint32_t bf[8][2];
#pragma unroll
            for (int nt = 0; nt < 8; ++nt) {
                const __half* bp = Bs + (wn + nt * 8 + gID) * ROWH + ks + 2 * tg;
                bf[nt][0] = *reinterpret_cast<const uint32_t*>(bp);
                bf[nt][1] = *reinterpret_cast<const uint32_t*>(bp + 8);
            }
#pragma unroll
            for (int mt = 0; mt < 4; ++mt)
#pragma unroll
                for (int nt = 0; nt < 8; ++nt)
                    mma_f16(acc[mt][nt], af[mt], bf[nt]);
        }
        __syncthreads();
    }

    // Epilogue: direct fp32 stores.
#pragma unroll
    for (int mt = 0; mt < 4; ++mt) {
        int r0 = bm + wm + mt * 16 + gID;
#pragma unroll
        for (int nt = 0; nt < 8; ++nt) {
            int c = bn + wn + nt * 8 + tg * 2;
            *reinterpret_cast<float2*>(C + (size_t)r0 * OUT_F + c) =
                make_float2(acc[mt][nt][0], acc[mt][nt][1]);
            *reinterpret_cast<float2*>(C + (size_t)(r0 + 8) * OUT_F + c) =
                make_float2(acc[mt][nt][2], acc[mt][nt][3]);
        }
    }
}

// ---------------------------------------------------------------------------
extern "C" void kernel_launch(void* const* d_in, const int* in_sizes, int n_in,
                              void* d_out, int out_size) {
    const float* x    = (const float*)d_in[0];
    const float* coef = (const float*)d_in[1];
    const float* grid = (const float*)d_in[2];
    float* out = (float*)d_out;

    basis_kernel<<<(M_ROWS * IN_F + 255) / 256, 256>>>(x, grid);
    wpack_kernel<<<(IN_F * OUT_F + 255) / 256, 256>>>(coef);

    static int smem_set = 0;
    if (!smem_set) {
        cudaFuncSetAttribute(gemm_kernel, cudaFuncAttributeMaxDynamicSharedMemorySize,
                             SMEM_BYTES);
        smem_set = 1;
    }
    dim3 g(OUT_F / BN, M_ROWS / BM);   // (2, 64) = 128 CTAs, one wave
    gemm_kernel<<<g, 256, SMEM_BYTES>>>(out);
}

// round 5
// speedup vs baseline: 1.9721x; 1.0187x over previous
#include <cuda_runtime.h>
#include <cuda_fp16.h>
#include <cstdint>

// Problem sizes (fixed by the reference)
#define M_ROWS 8192
#define IN_F   512
#define OUT_F  512
#define KDIM   (IN_F * 8)   // 4096

// ---------------------------------------------------------------------------
// Device scratch (allocation-free rule: __device__ globals)
// ---------------------------------------------------------------------------
__device__ __align__(16) __half g_Ah[(size_t)M_ROWS * KDIM]; // 64 MB bases (fp16)
__device__ __align__(16) __half g_Wh[(size_t)OUT_F * KDIM];  //  4 MB packed coeffs

// ---------------------------------------------------------------------------
// Kernel 1: bases. Select-free placement via funnel shift of packed halves.
// ---------------------------------------------------------------------------
__global__ void basis_kernel(const float* __restrict__ x,
                             const float* __restrict__ grid) {
    int idx = blockIdx.x * blockDim.x + threadIdx.x;
    if (idx >= M_ROWS * IN_F) return;

    float g0   = __ldg(grid);
    float invh = 1.0f / (__ldg(grid + 1) - g0);

    float xv = x[idx];
    float e  = __expf(2.0f * xv);
    float xn = 1.0f - 2.0f / (e + 1.0f);   // tanh(xv), ~1e-7 rel err

    float t  = (xn - g0) * invh;
    int   m  = (int)floorf(t);
    m = min(max(m, 3), 7);
    float u  = t - (float)m;

    float um = 1.0f - u;
    float u2 = u * u, u3 = u2 * u;
    const float s = 1.0f / 6.0f;
    float w0 = um * um * um * s;
    float w1 = (3.0f * u3 - 6.0f * u2 + 4.0f) * s;
    float w2 = (-3.0f * u3 + 3.0f * u2 + 3.0f * u + 1.0f) * s;
    float w3 = u3 * s;
    int j0 = m - 3;                        // in [0,4]

    // pack w0..w3 as 4 halves in 2 words, then shift left by 16*j0 bits
    // within a 128-bit (8-half) window.
    __half2 hA = __floats2half2_rn(w0, w1);
    __half2 hB = __floats2half2_rn(w2, w3);
    uint32_t u0 = *(uint32_t*)&hA;
    uint32_t u1 = *(uint32_t*)&hB;

    uint32_t b = (j0 & 1) << 4;            // 0 or 16
    uint32_t t0 = u0 << b;
    uint32_t t1 = __funnelshift_l(u0, u1, b);
    uint32_t t2 = __funnelshift_l(u1, 0u, b);
    int ws = j0 >> 1;                      // 0,1,2

    uint32_t o0 = (ws == 0) ? t0 : 0u;
    uint32_t o1 = (ws == 0) ? t1 : ((ws == 1) ? t0 : 0u);
    uint32_t o2 = (ws == 0) ? t2 : ((ws == 1) ? t1 : t0);
    uint32_t o3 = (ws == 1) ? t2 : ((ws == 2) ? t1 : 0u);

    *reinterpret_cast<uint4*>(g_Ah + (size_t)idx * 8) = make_uint4(o0, o1, o2, o3);
}

// ---------------------------------------------------------------------------
// Kernel 2: pack W[o][i*8+k] = C[i][o][k], fp16.
// ---------------------------------------------------------------------------
__global__ void wpack_kernel(const float* __restrict__ coef) {
    int t = blockIdx.x * blockDim.x + threadIdx.x;
    if (t >= IN_F * OUT_F) return;
    int i = t & (IN_F - 1);
    int o = t >> 9;

    const float4* src = reinterpret_cast<const float4*>(coef + ((size_t)i * OUT_F + o) * 8);
    float4 c0 = __ldg(src);
    float4 c1 = __ldg(src + 1);

    __half2 h0 = __floats2half2_rn(c0.x, c0.y);
    __half2 h1 = __floats2half2_rn(c0.z, c0.w);
    __half2 h2 = __floats2half2_rn(c1.x, c1.y);
    __half2 h3 = __floats2half2_rn(c1.z, c1.w);
    *reinterpret_cast<uint4*>(g_Wh + (size_t)o * KDIM + i * 8) =
        make_uint4(*(uint32_t*)&h0, *(uint32_t*)&h1, *(uint32_t*)&h2, *(uint32_t*)&h3);
}

// ---------------------------------------------------------------------------
// Kernel 3: GEMM via mma.sync m16n8k16 fp16->fp32, ldmatrix fragment loads.
// CTA 128x256, BK=32 halves, 3-stage cp.async, 8 warps (2x4), 64x64 warp tiles.
// ---------------------------------------------------------------------------
#define BM 128
#define BN 256
#define BK 32
#define ROWH 40                       // padded row (80B): LDSM conflict-free
#define STAGES 3
#define KT (KDIM / BK)                // 128
#define A_ST (BM * ROWH)
#define B_ST (BN * ROWH)
#define SMEM_BYTES (STAGES * (A_ST + B_ST) * 2)

__device__ __forceinline__ void cp16(void* smem, const void* gmem) {
    uint32_t sa = (uint32_t)__cvta_generic_to_shared(smem);
    asm volatile("cp.async.cg.shared.global [%0], [%1], 16;\n" :: "r"(sa), "l"(gmem));
}

__device__ __forceinline__ void ldsm_x4(uint32_t (&r)[4], uint32_t saddr) {
    asm volatile("ldmatrix.sync.aligned.m8n8.x4.shared.b16 {%0,%1,%2,%3}, [%4];"
                 : "=r"(r[0]), "=r"(r[1]), "=r"(r[2]), "=r"(r[3]) : "r"(saddr));
}

__device__ __forceinline__ void mma_f16(float (&d)[4], uint32_t a0, uint32_t a1,
                                        uint32_t a2, uint32_t a3,
                                        uint32_t b0, uint32_t b1) {
    asm volatile(
        "mma.sync.aligned.m16n8k16.row.col.f32.f16.f16.f32 "
        "{%0,%1,%2,%3}, {%4,%5,%6,%7}, {%8,%9}, {%0,%1,%2,%3};"
        : "+f"(d[0]), "+f"(d[1]), "+f"(d[2]), "+f"(d[3])
        : "r"(a0), "r"(a1), "r"(a2), "r"(a3), "r"(b0), "r"(b1));
}

__global__ void __launch_bounds__(256, 1) gemm_kernel(float* __restrict__ C) {
    extern __shared__ __half sm[];
    __half* AsBase = sm;
    __half* BsBase = sm + STAGES * A_ST;
    const uint32_t smem0 = (uint32_t)__cvta_generic_to_shared(sm);
    const uint32_t Bs0   = smem0 + STAGES * A_ST * 2;

    const int tid  = threadIdx.x;
    const int bm   = blockIdx.y * BM;
    const int bn   = blockIdx.x * BN;
    const int wid  = tid >> 5;
    const int lane = tid & 31;
    const int wm   = (wid >> 2) * 64;
    const int wn   = (wid & 3) * 64;
    const int gID  = lane >> 2;
    const int tg   = lane & 3;

    // ldmatrix lane addressing: row = tile_row + (lane&15), col = ks + 8*(lane>>4)
    const int lrow = lane & 15;
    const int lcol = (lane >> 4) << 3;

    float acc[4][8][4];
#pragma unroll
    for (int a = 0; a < 4; ++a)
#pragma unroll
        for (int b = 0; b < 8; ++b)
#pragma unroll
            for (int c = 0; c < 4; ++c) acc[a][b][c] = 0.0f;

    auto issue = [&](int s, int kt) {
        int k0 = kt * BK;
        __half* As = AsBase + s * A_ST;
        __half* Bs = BsBase + s * B_ST;
#pragma unroll
        for (int i = 0; i < 2; ++i) {
            int id = tid + 256 * i;
            int r = id >> 2, c = id & 3;
            cp16(As + r * ROWH + c * 8, g_Ah + (size_t)(bm + r) * KDIM + k0 + c * 8);
        }
#pragma unroll
        for (int i = 0; i < 4; ++i) {
            int id = tid + 256 * i;
            int r = id >> 2, c = id & 3;
            cp16(Bs + r * ROWH + c * 8, g_Wh + (size_t)(bn + r) * KDIM + k0 + c * 8);
        }
        asm volatile("cp.async.commit_group;\n");
    };

    issue(0, 0);
    issue(1, 1);

    for (int kt = 0; kt < KT; ++kt) {
        if (kt < KT - 1) {
            asm volatile("cp.async.wait_group 1;\n");
        } else {
            asm volatile("cp.async.wait_group 0;\n");
        }
        __syncthreads();

        if (kt + 2 < KT) issue((kt + 2) % STAGES, kt + 2);

        const int s = kt % STAGES;
        const uint32_t As_u = smem0 + (s * A_ST) * 2;
        const uint32_t Bs_u = Bs0 + (s * B_ST) * 2;

#pragma unroll
        for (int ks = 0; ks < BK; ks += 16) {
            uint32_t af[4][4];
#pragma unroll
            for (int mt = 0; mt < 4; ++mt)
                ldsm_x4(af[mt], As_u + ((wm + mt * 16 + lrow) * ROWH + ks + lcol) * 2);
            uint32_t bf[8][2];
#pragma unroll
            for (int j = 0; j < 4; ++j) {
                uint32_t r[4];
                ldsm_x4(r, Bs_u + ((wn + j * 16 + lrow) * ROWH + ks + lcol) * 2);
                bf[2 * j][0] = r[0]; bf[2 * j + 1][0] = r[1];
                bf[2 * j][1] = r[2]; bf[2 * j + 1][1] = r[3];
            }
#pragma unroll
            for (int mt = 0; mt < 4; ++mt)
#pragma unroll
                for (int nt = 0; nt < 8; ++nt)
                    mma_f16(acc[mt][nt], af[mt][0], af[mt][1], af[mt][2], af[mt][3],
                            bf[nt][0], bf[nt][1]);
        }
        __syncthreads();
    }

    // Epilogue: direct fp32 stores.
#pragma unroll
    for (int mt = 0; mt < 4; ++mt) {
        int r0 = bm + wm + mt * 16 + gID;
#pragma unroll
        for (int nt = 0; nt < 8; ++nt) {
            int c = bn + wn + nt * 8 + tg * 2;
            *reinterpret_cast<float2*>(C + (size_t)r0 * OUT_F + c) =
                make_float2(acc[mt][nt][0], acc[mt][nt][1]);
            *reinterpret_cast<float2*>(C + (size_t)(r0 + 8) * OUT_F + c) =
                make_float2(acc[mt][nt][2], acc[mt][nt][3]);
        }
    }
}

// ---------------------------------------------------------------------------
extern "C" void kernel_launch(void* const* d_in, const int* in_sizes, int n_in,
                              void* d_out, int out_size) {
    const float* x    = (const float*)d_in[0];
    const float* coef = (const float*)d_in[1];
    const float* grid = (const float*)d_in[2];
    float* out = (float*)d_out;

    basis_kernel<<<(M_ROWS * IN_F + 255) / 256, 256>>>(x, grid);
    wpack_kernel<<<(IN_F * OUT_F + 255) / 256, 256>>>(coef);

    static int smem_set = 0;
    if (!smem_set) {
        cudaFuncSetAttribute(gemm_kernel, cudaFuncAttributeMaxDynamicSharedMemorySize,
                             SMEM_BYTES);
        smem_set = 1;
    }
    dim3 g(OUT_F / BN, M_ROWS / BM);   // (2, 64) = 128 CTAs, one wave
    gemm_kernel<<<g, 256, SMEM_BYTES>>>(out);
}

// round 6
// speedup vs baseline: 2.0914x; 1.0605x over previous
#include <cuda_runtime.h>
#include <cuda_fp16.h>
#include <cstdint>

// Problem sizes (fixed by the reference)
#define M_ROWS 8192
#define IN_F   512
#define OUT_F  512
#define KDIM   (IN_F * 8)   // 4096

// ---------------------------------------------------------------------------
// Device scratch (allocation-free rule: __device__ globals)
// ---------------------------------------------------------------------------
__device__ __align__(16) __half g_Ah[(size_t)M_ROWS * KDIM]; // 64 MB bases (fp16)
__device__ __align__(16) __half g_Wh[(size_t)OUT_F * KDIM];  //  4 MB packed coeffs

// ---------------------------------------------------------------------------
// Kernel 1: bases, 2 elements per thread. Funnel-shift placement.
// ---------------------------------------------------------------------------
__device__ __forceinline__ uint4 basis_eval(float xv, float g0, float invh) {
    float e  = __expf(2.0f * xv);
    float xn = 1.0f - 2.0f / (e + 1.0f);   // tanh(xv)

    float t  = (xn - g0) * invh;
    int   m  = (int)floorf(t);
    m = min(max(m, 3), 7);
    float u  = t - (float)m;

    float um = 1.0f - u;
    float u2 = u * u, u3 = u2 * u;
    const float s = 1.0f / 6.0f;
    float w0 = um * um * um * s;
    float w1 = (3.0f * u3 - 6.0f * u2 + 4.0f) * s;
    float w2 = (-3.0f * u3 + 3.0f * u2 + 3.0f * u + 1.0f) * s;
    float w3 = u3 * s;
    int j0 = m - 3;                        // in [0,4]

    __half2 hA = __floats2half2_rn(w0, w1);
    __half2 hB = __floats2half2_rn(w2, w3);
    uint32_t u0 = *(uint32_t*)&hA;
    uint32_t u1 = *(uint32_t*)&hB;

    uint32_t b  = (j0 & 1) << 4;
    uint32_t t0 = u0 << b;
    uint32_t t1 = __funnelshift_l(u0, u1, b);
    uint32_t t2 = __funnelshift_l(u1, 0u, b);
    int ws = j0 >> 1;

    uint4 o;
    o.x = (ws == 0) ? t0 : 0u;
    o.y = (ws == 0) ? t1 : ((ws == 1) ? t0 : 0u);
    o.z = (ws == 0) ? t2 : ((ws == 1) ? t1 : t0);
    o.w = (ws == 1) ? t2 : ((ws == 2) ? t1 : 0u);
    return o;
}

__global__ void basis_kernel(const float* __restrict__ x,
                             const float* __restrict__ grid) {
    int p = blockIdx.x * blockDim.x + threadIdx.x;
    if (p >= M_ROWS * IN_F / 2) return;

    float g0   = __ldg(grid);
    float invh = 1.0f / (__ldg(grid + 1) - g0);

    float2 xv = reinterpret_cast<const float2*>(x)[p];
    uint4* dst = reinterpret_cast<uint4*>(g_Ah + (size_t)p * 16);
    dst[0] = basis_eval(xv.x, g0, invh);
    dst[1] = basis_eval(xv.y, g0, invh);
}

// ---------------------------------------------------------------------------
// Kernel 2: pack W[o][i*8+k] = C[i][o][k], fp16.
// ---------------------------------------------------------------------------
__global__ void wpack_kernel(const float* __restrict__ coef) {
    int t = blockIdx.x * blockDim.x + threadIdx.x;
    if (t >= IN_F * OUT_F) return;
    int i = t & (IN_F - 1);
    int o = t >> 9;

    const float4* src = reinterpret_cast<const float4*>(coef + ((size_t)i * OUT_F + o) * 8);
    float4 c0 = __ldg(src);
    float4 c1 = __ldg(src + 1);

    __half2 h0 = __floats2half2_rn(c0.x, c0.y);
    __half2 h1 = __floats2half2_rn(c0.z, c0.w);
    __half2 h2 = __floats2half2_rn(c1.x, c1.y);
    __half2 h3 = __floats2half2_rn(c1.z, c1.w);
    *reinterpret_cast<uint4*>(g_Wh + (size_t)o * KDIM + i * 8) =
        make_uint4(*(uint32_t*)&h0, *(uint32_t*)&h1, *(uint32_t*)&h2, *(uint32_t*)&h3);
}

// ---------------------------------------------------------------------------
// Kernel 3: GEMM, mma.sync m16n8k16 fp16->fp32, ldmatrix.
// CTA tile 224x128 (M padded to 8288 = 37*224), grid (4,37) = 148 CTAs =
// exactly one wave on 148 SMs. 8 warps 2x4, warp tile 112x32.
// ---------------------------------------------------------------------------
#define BM 224
#define BN 128
#define BK 32
#define ROWH 40                       // padded row (80B)
#define STAGES 3
#define KT (KDIM / BK)                // 128
#define A_ST (BM * ROWH)              // 8960 halves
#define B_ST (BN * ROWH)              // 5120 halves
#define SMEM_BYTES (STAGES * (A_ST + B_ST) * 2)   // 84480

__device__ __forceinline__ void cp16(void* smem, const void* gmem) {
    uint32_t sa = (uint32_t)__cvta_generic_to_shared(smem);
    asm volatile("cp.async.cg.shared.global [%0], [%1], 16;\n" :: "r"(sa), "l"(gmem));
}

__device__ __forceinline__ void ldsm_x4(uint32_t (&r)[4], uint32_t saddr) {
    asm volatile("ldmatrix.sync.aligned.m8n8.x4.shared.b16 {%0,%1,%2,%3}, [%4];"
                 : "=r"(r[0]), "=r"(r[1]), "=r"(r[2]), "=r"(r[3]) : "r"(saddr));
}

__device__ __forceinline__ void mma_f16(float (&d)[4], uint32_t a0, uint32_t a1,
                                        uint32_t a2, uint32_t a3,
                                        uint32_t b0, uint32_t b1) {
    asm volatile(
        "mma.sync.aligned.m16n8k16.row.col.f32.f16.f16.f32 "
        "{%0,%1,%2,%3}, {%4,%5,%6,%7}, {%8,%9}, {%0,%1,%2,%3};"
        : "+f"(d[0]), "+f"(d[1]), "+f"(d[2]), "+f"(d[3])
        : "r"(a0), "r"(a1), "r"(a2), "r"(a3), "r"(b0), "r"(b1));
}

__global__ void __launch_bounds__(256, 1) gemm_kernel(float* __restrict__ C) {
    extern __shared__ __half sm[];
    __half* AsBase = sm;
    __half* BsBase = sm + STAGES * A_ST;
    const uint32_t smem0 = (uint32_t)__cvta_generic_to_shared(sm);
    const uint32_t Bs0   = smem0 + STAGES * A_ST * 2;

    const int tid  = threadIdx.x;
    const int bm   = blockIdx.y * BM;
    const int bn   = blockIdx.x * BN;
    const int wid  = tid >> 5;
    const int lane = tid & 31;
    const int wm   = (wid >> 2) * 112;   // 0 / 112
    const int wn   = (wid & 3) * 32;     // 0..96
    const int gID  = lane >> 2;
    const int tg   = lane & 3;
    const int lrow = lane & 15;
    const int lcol = (lane >> 4) << 3;

    float acc[7][4][4];
#pragma unroll
    for (int a = 0; a < 7; ++a)
#pragma unroll
        for (int b = 0; b < 4; ++b)
#pragma unroll
            for (int c = 0; c < 4; ++c) acc[a][b][c] = 0.0f;

    auto issue = [&](int s, int kt) {
        int k0 = kt * BK;
        __half* As = AsBase + s * A_ST;
        __half* Bs = BsBase + s * B_ST;
#pragma unroll
        for (int i = 0; i < 4; ++i) {            // A: 224 rows x 4 chunks = 896
            int id = tid + 256 * i;
            if (id < BM * 4) {
                int r = id >> 2, c = id & 3;
                int gr = min(bm + r, M_ROWS - 1);  // clamp padded rows
                cp16(As + r * ROWH + c * 8, g_Ah + (size_t)gr * KDIM + k0 + c * 8);
            }
        }
#pragma unroll
        for (int i = 0; i < 2; ++i) {            // B: 128 rows x 4 chunks = 512
            int id = tid + 256 * i;
            int r = id >> 2, c = id & 3;
            cp16(Bs + r * ROWH + c * 8, g_Wh + (size_t)(bn + r) * KDIM + k0 + c * 8);
        }
        asm volatile("cp.async.commit_group;\n");
    };

    issue(0, 0);
    issue(1, 1);

    for (int kt = 0; kt < KT; ++kt) {
        if (kt < KT - 1) {
            asm volatile("cp.async.wait_group 1;\n");
        } else {
            asm volatile("cp.async.wait_group 0;\n");
        }
        __syncthreads();

        if (kt + 2 < KT) issue((kt + 2) % STAGES, kt + 2);

        const int s = kt % STAGES;
        const uint32_t As_u = smem0 + (s * A_ST) * 2;
        const uint32_t Bs_u = Bs0 + (s * B_ST) * 2;

#pragma unroll
        for (int ks = 0; ks < BK; ks += 16) {
            uint32_t af[7][4];
#pragma unroll
            for (int mt = 0; mt < 7; ++mt)
                ldsm_x4(af[mt], As_u + ((wm + mt * 16 + lrow) * ROWH + ks + lcol) * 2);
            uint32_t bf[4][2];
#pragma unroll
            for (int j = 0; j < 2; ++j) {
                uint32_t r[4];
                ldsm_x4(r, Bs_u + ((wn + j * 16 + lrow) * ROWH + ks + lcol) * 2);
                bf[2 * j][0] = r[0]; bf[2 * j + 1][0] = r[1];
                bf[2 * j][1] = r[2]; bf[2 * j + 1][1] = r[3];
            }
#pragma unroll
            for (int mt = 0; mt < 7; ++mt)
#pragma unroll
                for (int nt = 0; nt < 4; ++nt)
                    mma_f16(acc[mt][nt], af[mt][0], af[mt][1], af[mt][2], af[mt][3],
                            bf[nt][0], bf[nt][1]);
        }
        __syncthreads();
    }

    // Epilogue: guarded fp32 stores (padded M rows skipped).
#pragma unroll
    for (int mt = 0; mt < 7; ++mt) {
        int r0 = bm + wm + mt * 16 + gID;
#pragma unroll
        for (int nt = 0; nt < 4; ++nt) {
            int c = bn + wn + nt * 8 + tg * 2;
            if (r0 < M_ROWS)
                *reinterpret_cast<float2*>(C + (size_t)r0 * OUT_F + c) =
                    make_float2(acc[mt][nt][0], acc[mt][nt][1]);
            if (r0 + 8 < M_ROWS)
                *reinterpret_cast<float2*>(C + (size_t)(r0 + 8) * OUT_F + c) =
                    make_float2(acc[mt][nt][2], acc[mt][nt][3]);
        }
    }
}

// ---------------------------------------------------------------------------
extern "C" void kernel_launch(void* const* d_in, const int* in_sizes, int n_in,
                              void* d_out, int out_size) {
    const float* x    = (const float*)d_in[0];
    const float* coef = (const float*)d_in[1];
    const float* grid = (const float*)d_in[2];
    float* out = (float*)d_out;

    basis_kernel<<<(M_ROWS * IN_F / 2 + 255) / 256, 256>>>(x, grid);
    wpack_kernel<<<(IN_F * OUT_F + 255) / 256, 256>>>(coef);

    static int smem_set = 0;
    if (!smem_set) {
        cudaFuncSetAttribute(gemm_kernel, cudaFuncAttributeMaxDynamicSharedMemorySize,
                             SMEM_BYTES);
        smem_set = 1;
    }
    dim3 g(OUT_F / BN, 37);   // 4 x 37 = 148 CTAs = one full wave
    gemm_kernel<<<g, 256, SMEM_BYTES>>>(out);
}